// round 17
// baseline (speedup 1.0000x reference)
#include <cuda_runtime.h>
#include <cuda_fp16.h>
#include <mma.h>
#include <math.h>
#include <cstdint>

using namespace nvcuda;

#define NN 50000
#define NNP 50048           // 391 * 128, padded row count for GEMM tiles
#define NE 1600000
#define NG 64
#define BN_EPS 1e-5f

// ---------------- scratch (static __device__, no allocation) ----------------
__device__ float  g_deg[NN];
__device__ float  g_dinv[NN];
__device__ int    g_rowptr[NN + 1];
__device__ int    g_cursor[NN];
__device__ int    g_col[NE];
__device__ int    g_blksum[64];
__device__ int    g_blkoff[64];
__device__ int    g_gstart[NG + 1];
__device__ __half g_H[(size_t)NNP * 256];   // GEMM output / layer-1 Xagg
__device__ __half g_A[(size_t)NNP * 256];   // conv output (pre-BN), fp16
__device__ __half g_W0h[1280 * 128];        // fp16 weights (pre-converted)
__device__ __half g_W1h[128 * 256];
__device__ __half g_W2h[256 * 256];
__device__ double g_bnS0[128], g_bnQ0[128]; // per-layer BN accumulators
__device__ double g_bnS1[256], g_bnQ1[256];
__device__ double g_bnS2[256], g_bnQ2[256];
__device__ float  g_pool[NG * 256];
__device__ float  g_fc1[NG * 1024];

// BN affine from accumulated sums: returns (scale, shift)
__device__ __forceinline__ float2 bn_affine(int c, const double* S, const double* Q,
                                            const float* __restrict__ gamma,
                                            const float* __restrict__ beta) {
    double m = S[c] / (double)NN;
    double v = Q[c] / (double)NN - m * m;
    float sc = gamma[c] * rsqrtf((float)v + BN_EPS);
    return make_float2(sc, beta[c] - (float)m * sc);
}

// ---------------- init / degree / BN-accumulator zero ----------------
__global__ void k_prep() {
    int i = blockIdx.x * blockDim.x + threadIdx.x;
    if (i < NN) g_deg[i] = 1.0f;
    if (i < 128) { g_bnS0[i] = 0.0; g_bnQ0[i] = 0.0; }
    if (i < 256) {
        g_bnS1[i] = 0.0; g_bnQ1[i] = 0.0;
        g_bnS2[i] = 0.0; g_bnQ2[i] = 0.0;
    }
}

__global__ void k_deg_count(const int* __restrict__ dst) {
    int e = blockIdx.x * blockDim.x + threadIdx.x;
    if (e < NE) atomicAdd(&g_deg[dst[e]], 1.0f);
}

__global__ void k_dinv() {
    int i = blockIdx.x * blockDim.x + threadIdx.x;
    if (i < NN) g_dinv[i] = rsqrtf(g_deg[i]);   // deg >= 1 always (self loop)
}

// ---------------- weight fp32 -> fp16 (once per call, off critical path) ----
__global__ void k_wconv(const float* __restrict__ w, __half* __restrict__ o, int n8) {
    int i = blockIdx.x * blockDim.x + threadIdx.x;   // one uint4 out per thread
    if (i >= n8) return;
    const float4* wp = (const float4*)w + i * 2;
    float4 a = wp[0], b = wp[1];
    __half2 h[4] = { __floats2half2_rn(a.x, a.y), __floats2half2_rn(a.z, a.w),
                     __floats2half2_rn(b.x, b.y), __floats2half2_rn(b.z, b.w) };
    *(uint4*)(o + (size_t)i * 8) = *(uint4*)h;
}

// ---------------- 3-phase exclusive scan of (deg-1) -> rowptr ----------------
__global__ void k_scan1() {
    __shared__ int sh[1024];
    int tid = threadIdx.x;
    int i = blockIdx.x * 1024 + tid;
    int v = (i < NN) ? ((int)g_deg[i] - 1) : 0;
    sh[tid] = v;
    __syncthreads();
    for (int off = 1; off < 1024; off <<= 1) {
        int t = (tid >= off) ? sh[tid - off] : 0;
        __syncthreads();
        sh[tid] += t;
        __syncthreads();
    }
    if (i < NN) g_rowptr[i] = sh[tid] - v;     // block-local exclusive
    if (tid == 1023) g_blksum[blockIdx.x] = sh[1023];
}
__global__ void k_scan2(int nblk) {
    if (threadIdx.x != 0) return;
    int acc = 0;
    for (int b = 0; b < nblk; b++) { g_blkoff[b] = acc; acc += g_blksum[b]; }
    g_rowptr[NN] = acc;
}
__global__ void k_scan3() {
    int i = blockIdx.x * 1024 + threadIdx.x;
    if (i < NN) {
        int r = g_rowptr[i] + g_blkoff[blockIdx.x];
        g_rowptr[i] = r;
        g_cursor[i] = r;           // csr atomics return slot directly
    }
}

__global__ void k_csr(const int* __restrict__ src, const int* __restrict__ dst) {
    int e = blockIdx.x * blockDim.x + threadIdx.x;
    if (e >= NE) return;
    int p = atomicAdd(&g_cursor[dst[e]], 1);
    g_col[p] = src[e];
}

// ---- fp16 HMMA GEMM (m16n16k16), double-buffered smem + reg prefetch ------
// C[NNP,M](fp16) = epi( bn(A[*,K]) @ B[K,M] ),  B is fp16 (pre-converted)
// A_HALF=0: A fp32 raw.  A_HALF=1: A fp16.
// BN_IN=1: apply y = relu(sc[c]*x + sh[c]) to A on load; affine computed
//          from g_bnS1/g_bnQ1 + Gm/Bt in the smem fill.
// ADD_BIAS=1: epilogue adds Bias[col]; else epilogue scales row by g_dinv[row].
// Rows >= NA clamp to row 0 (garbage only in never-read pad rows).
#define ASTH 40    // As row stride in halves (32 + 8 pad)
#define BSTH 136   // Bs row stride in halves (128 + 8 pad)
template <int A_HALF, int BN_IN, int ADD_BIAS>
__global__ __launch_bounds__(256) void k_gemm_h(const void* __restrict__ Aptr,
                                                const __half* __restrict__ B,
                                                const float* __restrict__ Bias,
                                                const float* __restrict__ Gm,
                                                const float* __restrict__ Bt,
                                                __half* __restrict__ C,
                                                int NA, int K, int M) {
    __shared__ __half As[2][128 * ASTH];
    __shared__ __half Bs[2][32 * BSTH];
    __shared__ float  stg[8][16 * 16 + 8];
    __shared__ float  bns_s[256], bnt_s[256];
    const int bRow = blockIdx.y * 128;
    const int bCol = blockIdx.x * 128;
    const int tid = threadIdx.x;
    const int wid = tid >> 5;
    const int lane = tid & 31;
    const int wm = wid & 3;
    const int wn = wid >> 2;

    if (BN_IN) {
        for (int i = tid; i < K; i += 256) {
            float2 ab = bn_affine(i, g_bnS1, g_bnQ1, Gm, Bt);
            bns_s[i] = ab.x; bnt_s[i] = ab.y;
        }
        __syncthreads();   // bns_s/bnt_s visible to all threads before stA(0,0)
    }

    wmma::fragment<wmma::accumulator, 16, 16, 16, float> acc[2][4];
#pragma unroll
    for (int i = 0; i < 2; i++)
#pragma unroll
        for (int j = 0; j < 4; j++) wmma::fill_fragment(acc[i][j], 0.0f);

    // prefetch registers
    uint4  rbh[2];           // B tile: 32x128 half = 512 uint4, 2/thread
    float4 raf[4];           // A fp32: 128x32 fp32 = 1024 float4, 4/thread
    uint4  rah[2];           // A fp16: 128x32 half = 512 uint4, 2/thread

    auto ldB = [&](int t) {
        int k0 = t * 32;
#pragma unroll
        for (int l = 0; l < 2; l++) {
            int f = tid + l * 256;
            int row = f >> 4;              // 0..31 (16 uint4 per row)
            int c8 = (f & 15) * 8;
            rbh[l] = *(const uint4*)(B + (size_t)(k0 + row) * M + bCol + c8);
        }
    };
    auto stB = [&](int stage) {
#pragma unroll
        for (int l = 0; l < 2; l++) {
            int f = tid + l * 256;
            int row = f >> 4;
            int c8 = (f & 15) * 8;
            *(uint4*)&Bs[stage][row * BSTH + c8] = rbh[l];
        }
    };
    auto ldA = [&](int t) {
        int k0 = t * 32;
        if (A_HALF) {
            const __half* A = (const __half*)Aptr;
#pragma unroll
            for (int l = 0; l < 2; l++) {
                int f = tid + l * 256;
                int row = f >> 2;          // 0..127
                int u8 = (f & 3) * 8;      // half offset within row
                int gRow = bRow + row;
                if (gRow >= NA) gRow = 0;
                rah[l] = *(const uint4*)(A + (size_t)gRow * K + k0 + u8);
            }
        } else {
            const float* A = (const float*)Aptr;
#pragma unroll
            for (int l = 0; l < 4; l++) {
                int f = tid + l * 256;
                int row = f >> 3;          // 0..127 (8 float4 per row)
                int c4 = (f & 7) * 4;
                int gRow = bRow + row;
                if (gRow >= NA) gRow = 0;
                raf[l] = *(const float4*)(A + (size_t)gRow * K + k0 + c4);
            }
        }
    };
    auto stA = [&](int t, int stage) {
        if (A_HALF) {
            int k0 = t * 32;
#pragma unroll
            for (int l = 0; l < 2; l++) {
                int f = tid + l * 256;
                int row = f >> 2;
                int u8 = (f & 3) * 8;
                uint4 u = rah[l];
                if (BN_IN) {
                    int cb = k0 + u8;
                    __half2* hp = (__half2*)&u;
#pragma unroll
                    for (int q = 0; q < 4; q++) {
                        float2 fv = __half22float2(hp[q]);
                        int c = cb + q * 2;
                        fv.x = fmaxf(fv.x * bns_s[c] + bnt_s[c], 0.0f);
                        fv.y = fmaxf(fv.y * bns_s[c + 1] + bnt_s[c + 1], 0.0f);
                        hp[q] = __floats2half2_rn(fv.x, fv.y);
                    }
                }
                *(uint4*)&As[stage][row * ASTH + u8] = u;
            }
        } else {
#pragma unroll
            for (int l = 0; l < 4; l++) {
                int f = tid + l * 256;
                int row = f >> 3;
                int c4 = (f & 7) * 4;
                __half2 h0 = __floats2half2_rn(raf[l].x, raf[l].y);
                __half2 h1 = __floats2half2_rn(raf[l].z, raf[l].w);
                uint2 u = { *(unsigned*)&h0, *(unsigned*)&h1 };
                *(uint2*)&As[stage][row * ASTH + c4] = u;
            }
        }
    };

    const int T = K / 32;
    ldA(0); ldB(0);
    stA(0, 0); stB(0);
    if (T > 1) { ldA(1); ldB(1); }
    __syncthreads();

    for (int t = 0; t < T; t++) {
        const __half* as = As[t & 1];
        const __half* bs = Bs[t & 1];
#pragma unroll
        for (int ks = 0; ks < 2; ks++) {
            wmma::fragment<wmma::matrix_a, 16, 16, 16, __half, wmma::row_major> af[2];
            wmma::fragment<wmma::matrix_b, 16, 16, 16, __half, wmma::row_major> bf[4];
#pragma unroll
            for (int i = 0; i < 2; i++)
                wmma::load_matrix_sync(af[i], &as[(wm * 32 + i * 16) * ASTH + ks * 16], ASTH);
#pragma unroll
            for (int j = 0; j < 4; j++)
                wmma::load_matrix_sync(bf[j], &bs[(ks * 16) * BSTH + wn * 64 + j * 16], BSTH);
#pragma unroll
            for (int i = 0; i < 2; i++)
#pragma unroll
                for (int j = 0; j < 4; j++)
                    wmma::mma_sync(acc[i][j], af[i], bf[j], acc[i][j]);
        }
        if (t + 1 < T) {
            stA(t + 1, (t + 1) & 1); stB((t + 1) & 1);   // other buffer: no race
            if (t + 2 < T) { ldA(t + 2); ldB(t + 2); }
            __syncthreads();
        }
    }

    // epilogue: stage fp32 frag, apply dinv-scale or +bias, fp16 16B stores
#pragma unroll
    for (int i = 0; i < 2; i++)
#pragma unroll
        for (int j = 0; j < 4; j++) {
            wmma::store_matrix_sync(&stg[wid][0], acc[i][j], 16, wmma::mem_row_major);
            __syncwarp();
            int base = lane * 8;
            int r = base >> 4;          // 0..15
            int c = base & 15;          // 0 or 8
            const float* sp = &stg[wid][r * 16 + c];
            int row0 = bRow + wm * 32 + i * 16;
            int grow = row0 + r;
            int col0 = bCol + wn * 64 + j * 16;
            __half2 h[4];
            if (ADD_BIAS) {
#pragma unroll
                for (int q = 0; q < 4; q++) {
                    float b0 = Bias[col0 + c + q * 2];
                    float b1 = Bias[col0 + c + q * 2 + 1];
                    h[q] = __floats2half2_rn(sp[q * 2] + b0, sp[q * 2 + 1] + b1);
                }
            } else {
                float dr = g_dinv[grow < NN ? grow : 0];
#pragma unroll
                for (int q = 0; q < 4; q++)
                    h[q] = __floats2half2_rn(sp[q * 2] * dr, sp[q * 2 + 1] * dr);
            }
            *(uint4*)(C + (size_t)grow * M + col0 + c) = *(uint4*)h;
            __syncwarp();
        }
}

// ------- CSR gather aggregation + fused BN stats (warp per dst node) --------
// O[d] = dinv[d] * ( H'[d] + sum_{s in nbr(d)} H'[s] ) + bias,  H' = dinv.*H
// Per-block smem reduction of pre-BN outputs -> global double accumulators.
template <int NV4>   // 4-half groups per lane: C = NV4*128
__global__ void k_agg(const __half* __restrict__ H, __half* __restrict__ O,
                      const float* __restrict__ bias,
                      double* __restrict__ BS, double* __restrict__ BQ) {
    const int C = NV4 * 128;
    __shared__ float ssum[NV4 * 128], ssq[NV4 * 128];
    for (int i = threadIdx.x; i < C; i += 256) { ssum[i] = 0.f; ssq[i] = 0.f; }
    __syncthreads();

    int w = (blockIdx.x * blockDim.x + threadIdx.x) >> 5;
    int lane = threadIdx.x & 31;
    if (w < NN) {
        float di = g_dinv[w];
        float4 acc[NV4];
        const uint2* selfp = (const uint2*)(H + (size_t)w * C);
#pragma unroll
        for (int v = 0; v < NV4; v++) {
            uint2 u = selfp[lane + 32 * v];
            float2 a = __half22float2(*(__half2*)&u.x);
            float2 b = __half22float2(*(__half2*)&u.y);
            acc[v] = make_float4(a.x, a.y, b.x, b.y);
        }
        int p = g_rowptr[w], e = g_rowptr[w + 1];
        for (; p + 1 < e; p += 2) {
            int s0 = g_col[p], s1 = g_col[p + 1];
            const uint2* h0 = (const uint2*)(H + (size_t)s0 * C);
            const uint2* h1 = (const uint2*)(H + (size_t)s1 * C);
#pragma unroll
            for (int v = 0; v < NV4; v++) {
                uint2 u0 = h0[lane + 32 * v];
                uint2 u1 = h1[lane + 32 * v];
                float2 a0 = __half22float2(*(__half2*)&u0.x);
                float2 b0 = __half22float2(*(__half2*)&u0.y);
                float2 a1 = __half22float2(*(__half2*)&u1.x);
                float2 b1 = __half22float2(*(__half2*)&u1.y);
                acc[v].x += a0.x + a1.x;
                acc[v].y += a0.y + a1.y;
                acc[v].z += b0.x + b1.x;
                acc[v].w += b0.y + b1.y;
            }
        }
        if (p < e) {
            int s = g_col[p];
            const uint2* hp = (const uint2*)(H + (size_t)s * C);
#pragma unroll
            for (int v = 0; v < NV4; v++) {
                uint2 u = hp[lane + 32 * v];
                float2 a = __half22float2(*(__half2*)&u.x);
                float2 b = __half22float2(*(__half2*)&u.y);
                acc[v].x += a.x; acc[v].y += a.y;
                acc[v].z += b.x; acc[v].w += b.y;
            }
        }
#pragma unroll
        for (int v = 0; v < NV4; v++) {
            int c = (lane + 32 * v) * 4;
            float4 bb = *(const float4*)(bias + c);
            float4 o = make_float4(acc[v].x * di + bb.x, acc[v].y * di + bb.y,
                                   acc[v].z * di + bb.z, acc[v].w * di + bb.w);
            __half2 o0 = __floats2half2_rn(o.x, o.y);
            __half2 o1 = __floats2half2_rn(o.z, o.w);
            uint2 u = { *(unsigned*)&o0, *(unsigned*)&o1 };
            *(uint2*)(O + (size_t)w * C + c) = u;
            atomicAdd(&ssum[c + 0], o.x); atomicAdd(&ssq[c + 0], o.x * o.x);
            atomicAdd(&ssum[c + 1], o.y); atomicAdd(&ssq[c + 1], o.y * o.y);
            atomicAdd(&ssum[c + 2], o.z); atomicAdd(&ssq[c + 2], o.z * o.z);
            atomicAdd(&ssum[c + 3], o.w); atomicAdd(&ssq[c + 3], o.w * o.w);
        }
    }
    __syncthreads();
    for (int i = threadIdx.x; i < C; i += 256) {
        atomicAdd(&BS[i], (double)ssum[i]);
        atomicAdd(&BQ[i], (double)ssq[i]);
    }
}

// ---- layer-1 aggregate-before-transform: X[d] = dinv_d*(Σ dinv_s*f(A[s]) + dinv_d*f(A[d]))
// f(x) = relu(sc[c]*x + sh[c]), affine from accumulators. C = 128.
__device__ __forceinline__ float4 bnrelu4(uint2 u, float4 sc, float4 tc) {
    float2 a = __half22float2(*(__half2*)&u.x);
    float2 b = __half22float2(*(__half2*)&u.y);
    float4 r;
    r.x = fmaxf(a.x * sc.x + tc.x, 0.0f);
    r.y = fmaxf(a.y * sc.y + tc.y, 0.0f);
    r.z = fmaxf(b.x * sc.z + tc.z, 0.0f);
    r.w = fmaxf(b.y * sc.w + tc.w, 0.0f);
    return r;
}
__global__ void k_aggx(const __half* __restrict__ A0, __half* __restrict__ X,
                       const float* __restrict__ Gm, const float* __restrict__ Bt) {
    int w = (blockIdx.x * blockDim.x + threadIdx.x) >> 5;
    if (w >= NN) return;
    int lane = threadIdx.x & 31;
    int c4 = lane * 4;
    float di = g_dinv[w];
    float2 a0 = bn_affine(c4 + 0, g_bnS0, g_bnQ0, Gm, Bt);
    float2 a1 = bn_affine(c4 + 1, g_bnS0, g_bnQ0, Gm, Bt);
    float2 a2 = bn_affine(c4 + 2, g_bnS0, g_bnQ0, Gm, Bt);
    float2 a3 = bn_affine(c4 + 3, g_bnS0, g_bnQ0, Gm, Bt);
    float4 sc = make_float4(a0.x, a1.x, a2.x, a3.x);
    float4 tc = make_float4(a0.y, a1.y, a2.y, a3.y);

    uint2 us = *(const uint2*)(A0 + (size_t)w * 128 + c4);
    float4 fs = bnrelu4(us, sc, tc);
    float4 acc = make_float4(fs.x * di, fs.y * di, fs.z * di, fs.w * di);

    int p = g_rowptr[w], e = g_rowptr[w + 1];
    for (; p + 1 < e; p += 2) {
        int s0 = g_col[p], s1 = g_col[p + 1];
        float d0 = g_dinv[s0], d1 = g_dinv[s1];
        uint2 u0 = *(const uint2*)(A0 + (size_t)s0 * 128 + c4);
        uint2 u1 = *(const uint2*)(A0 + (size_t)s1 * 128 + c4);
        float4 f0 = bnrelu4(u0, sc, tc);
        float4 f1 = bnrelu4(u1, sc, tc);
        acc.x += d0 * f0.x + d1 * f1.x;
        acc.y += d0 * f0.y + d1 * f1.y;
        acc.z += d0 * f0.z + d1 * f1.z;
        acc.w += d0 * f0.w + d1 * f1.w;
    }
    if (p < e) {
        int s = g_col[p];
        float ds = g_dinv[s];
        uint2 u = *(const uint2*)(A0 + (size_t)s * 128 + c4);
        float4 f = bnrelu4(u, sc, tc);
        acc.x += ds * f.x; acc.y += ds * f.y;
        acc.z += ds * f.z; acc.w += ds * f.w;
    }
    __half2 o0 = __floats2half2_rn(acc.x * di, acc.y * di);
    __half2 o1 = __floats2half2_rn(acc.z * di, acc.w * di);
    uint2 u = { *(unsigned*)&o0, *(unsigned*)&o1 };
    *(uint2*)(X + (size_t)w * 128 + c4) = u;
}

// ---------------- BN stats for layer 1 (A1 = GEMM output) -------------------
#define BN_P 512   // row-partials per channel
__global__ void k_bnstats(const __half* __restrict__ h, int C) {
    int t = blockIdx.x * blockDim.x + threadIdx.x;
    if (t >= C * BN_P) return;
    int c = t & (C - 1);
    int p = t / C;
    float s = 0.f, q = 0.f;
    for (int r = p; r < NN; r += BN_P) {
        float x = __half2float(h[(size_t)r * C + c]);
        s += x; q += x * x;
    }
    atomicAdd(&g_bnS1[c], (double)s);
    atomicAdd(&g_bnQ1[c], (double)q);
}

// ---------------- global mean pool (sorted batch -> contiguous ranges) -------
__global__ void k_bounds(const int* __restrict__ batch) {
    int g = threadIdx.x;            // 0..NG (65 threads)
    if (g > NG) return;
    int lo = 0, hi = NN;            // lower_bound of g
    while (lo < hi) { int mid = (lo + hi) >> 1; if (batch[mid] < g) lo = mid + 1; else hi = mid; }
    g_gstart[g] = lo;
}

// pool applies layer-2 BN + ReLU on the fly (affine from accumulators)
__global__ void k_pool(const __half* __restrict__ h,
                       const float* __restrict__ Gm, const float* __restrict__ Bt) {
    int b = blockIdx.x;             // 64 blocks, 256 threads
    int c = threadIdx.x;
    int st = g_gstart[b], en = g_gstart[b + 1];
    float2 ab = bn_affine(c, g_bnS2, g_bnQ2, Gm, Bt);
    float s = 0.f;
    for (int r = st; r < en; r++) {
        float x = __half2float(h[(size_t)r * 256 + c]);
        s += fmaxf(x * ab.x + ab.y, 0.0f);
    }
    g_pool[b * 256 + c] = s / fmaxf((float)(en - st), 1.0f);
}

// ---------------- FC head ----------------
__global__ void k_fc1(const float* __restrict__ Wf0, const float* __restrict__ bf0) {
    int t = blockIdx.x * blockDim.x + threadIdx.x;
    if (t >= NG * 1024) return;
    int b = t >> 10, j = t & 1023;
    float s = bf0[j];
    const float* g = g_pool + b * 256;
    for (int c = 0; c < 256; c++) s += g[c] * Wf0[c * 1024 + j];
    g_fc1[t] = fmaxf(s, 0.0f);
}

__global__ void k_fc2(const float* __restrict__ Wf1, const float* __restrict__ bf1,
                      float* __restrict__ out) {
    int t = blockIdx.x * blockDim.x + threadIdx.x;
    if (t >= NG * 128) return;
    int b = t >> 7, j = t & 127;
    float s = bf1[j];
    const float* g = g_fc1 + b * 1024;
    for (int c = 0; c < 1024; c++) s += g[c] * Wf1[c * 128 + j];
    out[t] = s;
}

// ---------------- launcher ----------------
extern "C" void kernel_launch(void* const* d_in, const int* in_sizes, int n_in,
                              void* d_out, int out_size) {
    const float* x     = (const float*)d_in[0];
    const int*   ei    = (const int*)d_in[1];
    const int*   batch = (const int*)d_in[2];
    const float* Wg0 = (const float*)d_in[3];
    const float* bg0 = (const float*)d_in[4];
    const float* gm0 = (const float*)d_in[5];
    const float* bt0 = (const float*)d_in[6];
    const float* Wg1 = (const float*)d_in[7];
    const float* bg1 = (const float*)d_in[8];
    const float* gm1 = (const float*)d_in[9];
    const float* bt1 = (const float*)d_in[10];
    const float* Wg2 = (const float*)d_in[11];
    const float* bg2 = (const float*)d_in[12];
    const float* gm2 = (const float*)d_in[13];
    const float* bt2 = (const float*)d_in[14];
    const float* Wf0 = (const float*)d_in[15];
    const float* bf0 = (const float*)d_in[16];
    const float* Wf1 = (const float*)d_in[17];
    const float* bf1 = (const float*)d_in[18];
    float* out = (float*)d_out;

    const int* src = ei;           // edge_index[0]
    const int* dst = ei + NE;      // edge_index[1]

    __half* H; cudaGetSymbolAddress((void**)&H, g_H);
    __half* A; cudaGetSymbolAddress((void**)&A, g_A);
    __half* W0h; cudaGetSymbolAddress((void**)&W0h, g_W0h);
    __half* W1h; cudaGetSymbolAddress((void**)&W1h, g_W1h);
    __half* W2h; cudaGetSymbolAddress((void**)&W2h, g_W2h);
    double *S0, *Q0, *S2, *Q2;
    cudaGetSymbolAddress((void**)&S0, g_bnS0);
    cudaGetSymbolAddress((void**)&Q0, g_bnQ0);
    cudaGetSymbolAddress((void**)&S2, g_bnS2);
    cudaGetSymbolAddress((void**)&Q2, g_bnQ2);

    // side stream + fork/join events, created once on first (uncaptured) call
    static cudaStream_t s_side = nullptr;
    static cudaEvent_t  e_fork = nullptr, e_dinv = nullptr, e_csr = nullptr, e_w = nullptr;
    if (!s_side) {
        cudaStreamCreateWithFlags(&s_side, cudaStreamNonBlocking);
        cudaEventCreateWithFlags(&e_fork, cudaEventDisableTiming);
        cudaEventCreateWithFlags(&e_dinv, cudaEventDisableTiming);
        cudaEventCreateWithFlags(&e_csr, cudaEventDisableTiming);
        cudaEventCreateWithFlags(&e_w, cudaEventDisableTiming);
    }

    const int NBLK = (NN + 1023) / 1024;   // 49

    // ---- fork: side stream joins capture by waiting on main-stream event ----
    cudaEventRecord(e_fork, 0);
    cudaStreamWaitEvent(s_side, e_fork, 0);

    // ---- side stream: weight conversion (overlaps prep/deg/dinv on main) ----
    k_wconv<<<(1280 * 128 / 8 + 255) / 256, 256, 0, s_side>>>(Wg0, W0h, 1280 * 128 / 8);
    k_wconv<<<(128 * 256 / 8 + 255) / 256, 256, 0, s_side>>>(Wg1, W1h, 128 * 256 / 8);
    k_wconv<<<(256 * 256 / 8 + 255) / 256, 256, 0, s_side>>>(Wg2, W2h, 256 * 256 / 8);
    cudaEventRecord(e_w, s_side);

    // ---- main stream: degree + dinv (needed by GEMM-0 epilogue) ----
    k_prep<<<(NN + 255) / 256, 256>>>();
    k_deg_count<<<(NE + 255) / 256, 256>>>(dst);
    k_dinv<<<(NN + 255) / 256, 256>>>();
    cudaEventRecord(e_dinv, 0);

    // ---- side stream: CSR build + graph bounds, concurrent with GEMM-0 ----
    cudaStreamWaitEvent(s_side, e_dinv, 0);
    k_scan1<<<NBLK, 1024, 0, s_side>>>();
    k_scan2<<<1, 32, 0, s_side>>>(NBLK);
    k_scan3<<<NBLK, 1024, 0, s_side>>>();
    k_csr<<<(NE + 255) / 256, 256, 0, s_side>>>(src, dst);
    k_bounds<<<1, 96, 0, s_side>>>(batch);
    cudaEventRecord(e_csr, s_side);

    const int gy = NNP / 128;   // 391
    const int AGG_BLK = (NN * 32 + 255) / 256;   // 6250

    // ---- layer 0 (transform-first): H = dinv .* (x @ Wg0)  [overlaps CSR build]
    cudaStreamWaitEvent(0, e_w, 0);            // GEMM-0 needs fp16 weights
    k_gemm_h<0, 0, 0><<<dim3(1, gy), 256>>>(x, W0h, nullptr, nullptr, nullptr, H, NN, 1280, 128);
    cudaStreamWaitEvent(0, e_csr, 0);          // join: agg needs CSR
    k_agg<1><<<AGG_BLK, 256>>>(H, A, bg0, S0, Q0);   // fused BN0 stats

    // ---- layer 1 (aggregate-first): X = agg(relu(bn0(A0))); A1 = X @ Wg1 + b1
    k_aggx<<<AGG_BLK, 256>>>(A, H, gm0, bt0);
    k_gemm_h<1, 0, 1><<<dim3(2, gy), 256>>>(H, W1h, bg1, nullptr, nullptr, A, NN, 128, 256);
    k_bnstats<<<(256 * BN_P + 255) / 256, 256>>>(A, 256);

    // ---- layer 2 (transform-first): H = dinv .* (relu(bn1(A1)) @ Wg2); A2 = agg(H)+b2
    k_gemm_h<1, 1, 0><<<dim3(2, gy), 256>>>(A, W2h, nullptr, gm1, bt1, H, NNP, 256, 256);
    k_agg<2><<<AGG_BLK, 256>>>(H, A, bg2, S2, Q2);   // fused BN2 stats

    // ---- pool (applies bn2 + relu from accumulators) + FC head
    k_pool<<<NG, 256>>>(A, gm2, bt2);
    k_fc1<<<(NG * 1024 + 255) / 256, 256>>>(Wf0, bf0);
    k_fc2<<<(NG * 128 + 255) / 256, 256>>>(Wf1, bf1, out);
}